// round 17
// baseline (speedup 1.0000x reference)
#include <cuda_runtime.h>
#include <cuda_bf16.h>
#include <cstdint>
#include <math.h>

// Problem constants
#define NB 32768   // batch
#define TT 9       // time steps (T-1)
#define DD 81      // input dim
#define HH 128     // hidden
#define NG 512     // 4*HH gates
#define KW 96      // w_in K padded (81 -> 96)
#define NJ 14      // k-steps of 16: 6 w_in + 8 h

// Tiling: BM=64 rows/CTA (512 CTAs), 256 threads = 8 warps (2m x 4n), 2 CTAs/SM
#define BM 64
#define NTH 256
#define AST 464    // A row stride bytes (224 bf16; 464%128=80 -> conflict-free)
#define TMPST 132  // tmp row stride floats (conflict-free for quad pattern)

// SMEM map (bytes) — 86272 per CTA -> 2 CTAs/SM
#define SM_BIAS 0          // 2048
#define SM_A_HI 2048       // 64*464 = 29696 (w_in cols 0..95 | h cols 96..223)
#define SM_ATT  31744      // 64*81*4 = 20736
#define SM_TMP  52480      // 64*132*4 = 33792
#define SM_TOTAL 86272

// device scratch: weights in mma-fragment order.
// index = ((q*16 + ntile)*14 + j)*32 + lane ; value = (b0h, b1h, b0l, b1l)
// where n = q*128 + ntile*8 + (lane>>2), k0 = j*16 + 2*(lane&3):
//   b0 = (W[n][k0], W[n][k0+1]), b1 = (W[n][k0+8], W[n][k0+9])
__device__ __align__(16) uint4 g_Bf[4 * 16 * NJ * 32];
__device__ float g_bias[NG];

// ---------------------------------------------------------------------------
// prep: build fragment-ordered bf16 hi/lo weights; fuse biases.
// ---------------------------------------------------------------------------
__device__ __forceinline__ float w_elem(const float* W_ih, const float* W_hh,
                                        int n, int kk) {
    if (kk < DD) return W_ih[n * DD + kk];
    if (kk < KW) return 0.f;
    return W_hh[n * HH + (kk - KW)];
}

__global__ void prep_kernel(const float* __restrict__ W_ih,
                            const float* __restrict__ W_hh,
                            const float* __restrict__ b_ih,
                            const float* __restrict__ b_hh) {
    int idx = blockIdx.x * blockDim.x + threadIdx.x;   // 28672 threads
    if (idx < 4 * 16 * NJ * 32) {
        int lane = idx & 31;
        int r = idx >> 5;
        int j = r % NJ;
        int r2 = r / NJ;
        int ntile = r2 & 15;
        int q = r2 >> 4;
        int n = q * 128 + ntile * 8 + (lane >> 2);
        int k0 = j * 16 + (lane & 3) * 2;
        float w00 = w_elem(W_ih, W_hh, n, k0);
        float w01 = w_elem(W_ih, W_hh, n, k0 + 1);
        float w10 = w_elem(W_ih, W_hh, n, k0 + 8);
        float w11 = w_elem(W_ih, W_hh, n, k0 + 9);
        __nv_bfloat16 h00 = __float2bfloat16(w00), h01 = __float2bfloat16(w01);
        __nv_bfloat16 h10 = __float2bfloat16(w10), h11 = __float2bfloat16(w11);
        __nv_bfloat162 B0H(h00, h01), B1H(h10, h11);
        __nv_bfloat162 B0L(__float2bfloat16(w00 - __bfloat162float(h00)),
                           __float2bfloat16(w01 - __bfloat162float(h01)));
        __nv_bfloat162 B1L(__float2bfloat16(w10 - __bfloat162float(h10)),
                           __float2bfloat16(w11 - __bfloat162float(h11)));
        uint4 v;
        v.x = *reinterpret_cast<uint32_t*>(&B0H);
        v.y = *reinterpret_cast<uint32_t*>(&B1H);
        v.z = *reinterpret_cast<uint32_t*>(&B0L);
        v.w = *reinterpret_cast<uint32_t*>(&B1L);
        g_Bf[idx] = v;
    }
    if (idx < NG) g_bias[idx] = b_ih[idx] + b_hh[idx];
}

// ---------------------------------------------------------------------------
// helpers
// ---------------------------------------------------------------------------
__device__ __forceinline__ uint32_t smem_u32(const void* p) {
    uint32_t a;
    asm("{ .reg .u64 t; cvta.to.shared.u64 t, %1; cvt.u32.u64 %0, t; }" : "=r"(a) : "l"(p));
    return a;
}
__device__ __forceinline__ void ldsm_x4(uint32_t addr, uint32_t* r) {
    asm volatile("ldmatrix.sync.aligned.m8n8.x4.shared.b16 {%0,%1,%2,%3}, [%4];"
                 : "=r"(r[0]), "=r"(r[1]), "=r"(r[2]), "=r"(r[3]) : "r"(addr));
}
__device__ __forceinline__ void mma16816(float* d, const uint32_t* a,
                                         uint32_t b0, uint32_t b1) {
    asm volatile(
        "mma.sync.aligned.m16n8k16.row.col.f32.bf16.bf16.f32 "
        "{%0,%1,%2,%3}, {%4,%5,%6,%7}, {%8,%9}, {%0,%1,%2,%3};"
        : "+f"(d[0]), "+f"(d[1]), "+f"(d[2]), "+f"(d[3])
        : "r"(a[0]), "r"(a[1]), "r"(a[2]), "r"(a[3]), "r"(b0), "r"(b1));
}
__device__ __forceinline__ float tanh_fast(float x) {
    float y;
    asm("tanh.approx.f32 %0, %1;" : "=f"(y) : "f"(x));
    return y;
}
__device__ __forceinline__ float sig_fast(float x) {
    return fmaf(0.5f, tanh_fast(0.5f * x), 0.5f);
}
__device__ __forceinline__ uint32_t pack_bf16x2(float v0, float v1) {
    __nv_bfloat162 H(__float2bfloat16(v0), __float2bfloat16(v1));
    return *reinterpret_cast<uint32_t*>(&H);
}
// gate order i(0) -> g(2) -> f(1) -> o(3)
__device__ __forceinline__ int gate_of(int cc) {
    return (cc == 0) ? 0 : (cc == 1) ? 2 : (cc == 2) ? 1 : 3;
}

// stage w_in A tile for step t: w_in = att * x; also write input_weighted.
__device__ __forceinline__ void stage_win(const float* __restrict__ x,
                                          float* __restrict__ out_w,
                                          char* smem_c, int b0, int t, int tid) {
    const float* att_s = (const float*)(smem_c + SM_ATT);
    for (int p = tid; p < BM * 41; p += NTH) {
        int m = p / 41;
        int d = (p - m * 41) * 2;
        const float* src = x + (((size_t)(b0 + m)) * TT + t) * DD + d;
        float* dst = out_w + (((size_t)(b0 + m)) * TT + t) * DD + d;
        float v0 = att_s[m * DD + d] * src[0];
        float v1 = 0.f;
        dst[0] = v0;
        if (d + 1 < DD) {
            v1 = att_s[m * DD + d + 1] * src[1];
            dst[1] = v1;
        }
        *(uint32_t*)(smem_c + SM_A_HI + m * AST + d * 2) = pack_bf16x2(v0, v1);
    }
}

// ---------------------------------------------------------------------------
// fused attention + recurrent HMMA kernel: 1 CTA = 64 rows, 256 threads,
// 2 CTAs/SM. B operands loaded fragment-direct from gmem (L2-resident).
// ---------------------------------------------------------------------------
__global__ __launch_bounds__(NTH, 2)
void rnn_tc_kernel(const float* __restrict__ x,
                   const float* __restrict__ W_attn,
                   float* __restrict__ out_w,
                   float* __restrict__ out_enc) {
    extern __shared__ char smem_c[];
    const uint32_t smem_base = smem_u32(smem_c);
    const int tid = threadIdx.x;
    const int wid = tid >> 5;
    const int lane = tid & 31;
    const int mw = wid & 1;        // 2 m-warps (rows 32*mw..)
    const int nw = wid >> 1;       // 4 n-warps (cols 32*nw..)
    const int b0 = blockIdx.x * BM;

    float* bias_s = (float*)(smem_c + SM_BIAS);
    float* att_s  = (float*)(smem_c + SM_ATT);
    float2* tmp2  = (float2*)(smem_c + SM_TMP);
    for (int i = tid; i < NG; i += NTH) bias_s[i] = g_bias[i];
    {   // zero A_HI: 29696/16 = 1856 uint4
        uint4 z = make_uint4(0, 0, 0, 0);
        uint4* a4 = (uint4*)(smem_c + SM_A_HI);
        for (int i = tid; i < 1856; i += NTH) a4[i] = z;
    }

    // ---- fused attention: a[m][d] = softmax_d(sum_t x[m,t,d]*Wx[t]) ----
    {
        float wx[TT];
#pragma unroll
        for (int tt = 0; tt < TT; tt++) wx[tt] = W_attn[2 * HH + tt];
#pragma unroll 1
        for (int rr = 0; rr < BM / 8; rr++) {      // 8 iterations, 8 warps
            const int m = rr * 8 + wid;
            const float* xb = x + (size_t)(b0 + m) * TT * DD;
            float pre[3];
#pragma unroll
            for (int ii = 0; ii < 3; ii++) {
                int d = lane + 32 * ii;
                float p = 0.f;
#pragma unroll
                for (int tt = 0; tt < TT; tt++) {
                    float v = (d < DD) ? xb[tt * DD + d] : 0.f;
                    p = fmaf(v, wx[tt], p);
                }
                pre[ii] = (d < DD) ? p : -3.0e38f;
            }
            float mx = fmaxf(pre[0], fmaxf(pre[1], pre[2]));
#pragma unroll
            for (int o = 16; o > 0; o >>= 1)
                mx = fmaxf(mx, __shfl_xor_sync(0xffffffffu, mx, o));
            float ev[3];
            float sum = 0.f;
#pragma unroll
            for (int ii = 0; ii < 3; ii++) {
                int d = lane + 32 * ii;
                ev[ii] = (d < DD) ? __expf(pre[ii] - mx) : 0.f;
                sum += ev[ii];
            }
#pragma unroll
            for (int o = 16; o > 0; o >>= 1)
                sum += __shfl_xor_sync(0xffffffffu, sum, o);
            float inv = 1.f / sum;
#pragma unroll
            for (int ii = 0; ii < 3; ii++) {
                int d = lane + 32 * ii;
                if (d < DD) att_s[m * DD + d] = ev[ii] * inv;
            }
        }
    }
    __syncthreads();   // att_s + zeroed A visible

    stage_win(x, out_w, smem_c, b0, 0, tid);
    __syncthreads();   // w_in(t=0) visible

    // lane-resolved A ldmatrix base
    const uint32_t aHiB = smem_base + SM_A_HI + (mw * 32 + (lane & 15)) * AST
                        + ((lane >> 4) & 1) * 16;

    float c_r[2][4][4];
#pragma unroll
    for (int im = 0; im < 2; im++)
#pragma unroll
        for (int in = 0; in < 4; in++)
#pragma unroll
            for (int r = 0; r < 4; r++) c_r[im][in][r] = 0.f;

#pragma unroll 1
    for (int s = 0; s < 4 * TT; s++) {
        const int t = s >> 2;
        const int q = gate_of(s & 3);
        const int jm = (t > 0) ? NJ : 6;

        // per-gate fragment base: tiles nw*4 .. nw*4+3
        const uint4* bq = g_Bf + ((size_t)(q * 16 + nw * 4) * NJ) * 32 + lane;

        float acc[2][4][4];
#pragma unroll
        for (int im = 0; im < 2; im++)
#pragma unroll
            for (int in = 0; in < 4; in++)
#pragma unroll
                for (int r = 0; r < 4; r++) acc[im][in][r] = 0.f;

        uint4 bb[2][4];
#pragma unroll
        for (int in = 0; in < 4; in++) bb[0][in] = bq[in * (NJ * 32)];

#pragma unroll 1
        for (int j = 0; j < jm; j++) {
            const int cb = j & 1;
            if (j + 1 < jm) {
#pragma unroll
                for (int in = 0; in < 4; in++)
                    bb[cb ^ 1][in] = bq[in * (NJ * 32) + (j + 1) * 32];
            }
            uint32_t ah[2][4];
#pragma unroll
            for (int im = 0; im < 2; im++)
                ldsm_x4(aHiB + im * 16 * AST + j * 32, ah[im]);
#pragma unroll
            for (int im = 0; im < 2; im++) {
#pragma unroll
                for (int in = 0; in < 4; in++) {
                    mma16816(acc[im][in], ah[im], bb[cb][in].x, bb[cb][in].y);  // hi
                    mma16816(acc[im][in], ah[im], bb[cb][in].z, bb[cb][in].w);  // lo
                }
            }
        }

        if (q == 3) __syncthreads();   // all A readers (incl. h cols) done

        // ---- elementwise on gate q ----
#pragma unroll
        for (int im = 0; im < 2; im++) {
#pragma unroll
            for (int in = 0; in < 4; in++) {
#pragma unroll
                for (int rh = 0; rh < 2; rh++) {
                    const int m = mw * 32 + im * 16 + (lane >> 2) + rh * 8;
                    const int n0 = nw * 32 + in * 8 + (lane & 3) * 2;
                    const int ti = m * (TMPST / 2) + (n0 >> 1);
                    float g0 = acc[im][in][rh * 2]     + bias_s[q * HH + n0];
                    float g1 = acc[im][in][rh * 2 + 1] + bias_s[q * HH + n0 + 1];
                    if (q == 0) {
                        tmp2[ti] = make_float2(sig_fast(g0), sig_fast(g1));
                    } else if (q == 2) {
                        float2 v = tmp2[ti];
                        v.x *= tanh_fast(g0);
                        v.y *= tanh_fast(g1);
                        tmp2[ti] = v;
                    } else if (q == 1) {
                        float2 v = tmp2[ti];
                        c_r[im][in][rh * 2] =
                            sig_fast(g0) * c_r[im][in][rh * 2] + v.x;
                        c_r[im][in][rh * 2 + 1] =
                            sig_fast(g1) * c_r[im][in][rh * 2 + 1] + v.y;
                    } else {
                        float h0 = sig_fast(g0) * tanh_fast(c_r[im][in][rh * 2]);
                        float h1 = sig_fast(g1) * tanh_fast(c_r[im][in][rh * 2 + 1]);
                        *(float2*)(out_enc + (((size_t)(b0 + m)) * TT + t) * HH + n0) =
                            make_float2(h0, h1);
                        if (t + 1 < TT)
                            *(uint32_t*)(smem_c + SM_A_HI + m * AST + (KW + n0) * 2) =
                                pack_bf16x2(h0, h1);
                    }
                }
            }
        }

        if (q == 3) {
            if (t + 1 < TT) stage_win(x, out_w, smem_c, b0, t + 1, tid);
            __syncthreads();   // h + w_in writes visible before next step's GEMMs
        }
    }
}

// ---------------------------------------------------------------------------
extern "C" void kernel_launch(void* const* d_in, const int* in_sizes, int n_in,
                              void* d_out, int out_size) {
    const float* x      = (const float*)d_in[0];
    const float* W_attn = (const float*)d_in[1];
    // d_in[2] = b_attn: cancels in softmax, unused
    const float* W_ih   = (const float*)d_in[3];
    const float* W_hh   = (const float*)d_in[4];
    const float* b_ih   = (const float*)d_in[5];
    const float* b_hh   = (const float*)d_in[6];

    float* out     = (float*)d_out;
    float* out_w   = out;                           // (B, 9, 81)
    float* out_enc = out + (size_t)NB * TT * DD;    // (B, 9, 128)

    prep_kernel<<<112, 256>>>(W_ih, W_hh, b_ih, b_hh);

    cudaFuncSetAttribute(rnn_tc_kernel, cudaFuncAttributeMaxDynamicSharedMemorySize, SM_TOTAL);
    rnn_tc_kernel<<<NB / BM, NTH, SM_TOTAL>>>(x, W_attn, out_w, out_enc);
}